// round 1
// baseline (speedup 1.0000x reference)
#include <cuda_runtime.h>

#define BATCH   2
#define HEADS   16
#define SEQ     2048
#define DKV     64
#define DMODEL  1024
#define MTOT    (BATCH * SEQ)      // 4096 rows
#define BIAS_PAD    4352
#define BIAS_CENTER 2176

#define QR 128   // q rows per attention CTA (1 per thread)
#define KT 32    // k rows per inner tile

// ---------------- scratch (device globals: allocation-guard safe) ----------
__device__ float g_q[BATCH * HEADS * SEQ * DKV];
__device__ float g_k[BATCH * HEADS * SEQ * DKV];
__device__ float g_v[BATCH * HEADS * SEQ * DKV];
__device__ float g_attn[MTOT * DMODEL];
__device__ float g_bias[HEADS * BIAS_PAD];

// ---------------- T5 relative-position bias, per head per delta -------------
__global__ void bias_kernel(const float* __restrict__ table) {
    int i = blockIdx.x * blockDim.x + threadIdx.x;
    if (i >= HEADS * BIAS_PAD) return;
    int h = i / BIAS_PAD;
    int delta = (i % BIAS_PAD) - BIAS_CENTER;   // delta = k - q
    float v = 0.0f;
    int rp = delta < 0 ? -delta : delta;
    if (rp <= SEQ - 1) {
        int base = (delta > 0) ? 16 : 0;
        int bucket;
        if (rp < 8) {
            bucket = base + rp;
        } else {
            // mirrors jnp: 8 + int32(log(rp/8)/log(16) * 8), clamped to 15
            float ratio = logf((float)rp * 0.125f) / (float)2.772588722239781;
            int rpl = 8 + (int)(ratio * 8.0f);
            bucket = base + (rpl < 15 ? rpl : 15);
        }
        v = table[bucket * HEADS + h];
    }
    g_bias[i] = v;
}

// ---------------- SGEMM 128x128 tile, BK=8, 8x8 per-thread ------------------
// C[M=4096, N=1024] = A[4096,1024] @ B[1024,1024]
// a_is_gattn: A comes from g_attn instead of Aext
// c_sel: 0 -> Cext (row-major), 1/2/3 -> g_q/g_k/g_v with (b,h,s,d) layout
__global__ __launch_bounds__(256) void sgemm128(const float* __restrict__ Aext,
                                                int a_is_gattn,
                                                const float* __restrict__ B,
                                                float* __restrict__ Cext,
                                                int c_sel, int head_layout) {
    const int K = DMODEL, N = DMODEL;
    const float* A = a_is_gattn ? g_attn : Aext;

    __shared__ __align__(16) float As[8][128];
    __shared__ __align__(16) float Bs[8][128];

    int tid = threadIdx.x;
    int m0 = blockIdx.y * 128;
    int n0 = blockIdx.x * 128;
    int tx = tid & 15;          // 0..15 -> 8 output cols
    int ty = tid >> 4;          // 0..15 -> 8 output rows

    int arow = tid >> 1;        // 0..127
    int acol = (tid & 1) * 4;   // 0 or 4
    int brow = tid >> 5;        // 0..7
    int bcol = (tid & 31) * 4;  // 0..124

    const float* Ap = A + (size_t)(m0 + arow) * K + acol;
    const float* Bp = B + (size_t)brow * N + n0 + bcol;

    float acc[8][8];
#pragma unroll
    for (int i = 0; i < 8; i++)
#pragma unroll
        for (int j = 0; j < 8; j++) acc[i][j] = 0.0f;

    for (int k0 = 0; k0 < K; k0 += 8) {
        float4 av = *(const float4*)Ap; Ap += 8;
        float4 bv = *(const float4*)Bp; Bp += 8 * N;
        As[acol + 0][arow] = av.x;
        As[acol + 1][arow] = av.y;
        As[acol + 2][arow] = av.z;
        As[acol + 3][arow] = av.w;
        *(float4*)&Bs[brow][bcol] = bv;
        __syncthreads();
#pragma unroll
        for (int kk = 0; kk < 8; kk++) {
            float4 a0 = *(const float4*)&As[kk][ty * 8];
            float4 a1 = *(const float4*)&As[kk][ty * 8 + 4];
            float4 b0 = *(const float4*)&Bs[kk][tx * 8];
            float4 b1 = *(const float4*)&Bs[kk][tx * 8 + 4];
            float a[8] = {a0.x, a0.y, a0.z, a0.w, a1.x, a1.y, a1.z, a1.w};
            float b[8] = {b0.x, b0.y, b0.z, b0.w, b1.x, b1.y, b1.z, b1.w};
#pragma unroll
            for (int i = 0; i < 8; i++)
#pragma unroll
                for (int j = 0; j < 8; j++)
                    acc[i][j] = fmaf(a[i], b[j], acc[i][j]);
        }
        __syncthreads();
    }

    float* Cq = (c_sel == 1) ? g_q : (c_sel == 2) ? g_k : g_v;
#pragma unroll
    for (int i = 0; i < 8; i++) {
        int r = m0 + ty * 8 + i;
#pragma unroll
        for (int j = 0; j < 8; j++) {
            int c = n0 + tx * 8 + j;
            float v = acc[i][j];
            if (head_layout) {
                int b = r >> 11;       // r / SEQ
                int s = r & (SEQ - 1);
                int h = c >> 6;        // c / DKV
                int d = c & (DKV - 1);
                Cq[(((size_t)(b * HEADS + h) * SEQ + s) << 6) + d] = v;
            } else {
                Cext[(size_t)r * N + c] = v;
            }
        }
    }
}

// ---------------- flash attention: 1 thread = 1 q row -----------------------
__global__ __launch_bounds__(128) void attn_kernel() {
    int tid = threadIdx.x;
    int qt = blockIdx.x, h = blockIdx.y, b = blockIdx.z;
    int bh = b * HEADS + h;
    int q0 = qt * QR;
    int qi = q0 + tid;

    __shared__ __align__(16) float4 Ks4[KT * 16];   // 32 x 64 f32
    __shared__ __align__(16) float4 Vs4[KT * 16];
    __shared__ float Ss[KT * QR];                   // raw scores, column per thread
    __shared__ float bias_s[KT + QR];               // 160 entries

    float4 q4[16], o4[16];
    const float4* qp = (const float4*)(g_q + (((size_t)bh * SEQ + qi) << 6));
#pragma unroll
    for (int i = 0; i < 16; i++) {
        q4[i] = qp[i];
        o4[i] = make_float4(0.f, 0.f, 0.f, 0.f);
    }

    float m = -1e30f, l = 0.0f;

    for (int kt = 0; kt < SEQ / KT; kt++) {
        int kbase = kt * KT;
        const float4* kp = (const float4*)(g_k + (((size_t)bh * SEQ + kbase) << 6));
        const float4* vp = (const float4*)(g_v + (((size_t)bh * SEQ + kbase) << 6));

        __syncthreads();   // previous iteration's reads done
#pragma unroll
        for (int i = 0; i < 4; i++) {
            Ks4[tid + i * 128] = kp[tid + i * 128];
            Vs4[tid + i * 128] = vp[tid + i * 128];
        }
        {
            // bias_s[t] covers delta = kbase + (t - (QR-1)) - q0
            const float* bb = g_bias + h * BIAS_PAD + (BIAS_CENTER - (QR - 1)) - q0 + kbase;
            bias_s[tid] = bb[tid];
            if (tid < KT) bias_s[QR + tid] = bb[QR + tid];
        }
        __syncthreads();

        // ---- scores: s_j = q . k_j + bias(j - tid) ----
        float mt = -1e30f;
#pragma unroll 4
        for (int j = 0; j < KT; j++) {
            float s0 = 0.f, s1 = 0.f, s2 = 0.f, s3 = 0.f;
#pragma unroll
            for (int d4 = 0; d4 < 16; d4++) {
                float4 kk = Ks4[j * 16 + d4];
                float4 qq = q4[d4];
                s0 = fmaf(qq.x, kk.x, s0);
                s1 = fmaf(qq.y, kk.y, s1);
                s2 = fmaf(qq.z, kk.z, s2);
                s3 = fmaf(qq.w, kk.w, s3);
            }
            float sj = (s0 + s1) + (s2 + s3);
            sj += bias_s[j - tid + (QR - 1)];
            Ss[j * QR + tid] = sj;
            mt = fmaxf(mt, sj);
        }

        // ---- online softmax rescale ----
        float mnew = fmaxf(m, mt);
        float corr = __expf(m - mnew);
#pragma unroll
        for (int i = 0; i < 16; i++) {
            o4[i].x *= corr; o4[i].y *= corr; o4[i].z *= corr; o4[i].w *= corr;
        }

        // ---- P.V accumulate ----
        float ssum = 0.f;
#pragma unroll 4
        for (int j = 0; j < KT; j++) {
            float p = __expf(Ss[j * QR + tid] - mnew);
            ssum += p;
#pragma unroll
            for (int d4 = 0; d4 < 16; d4++) {
                float4 vv = Vs4[j * 16 + d4];
                o4[d4].x = fmaf(p, vv.x, o4[d4].x);
                o4[d4].y = fmaf(p, vv.y, o4[d4].y);
                o4[d4].z = fmaf(p, vv.z, o4[d4].z);
                o4[d4].w = fmaf(p, vv.w, o4[d4].w);
            }
        }
        l = l * corr + ssum;
        m = mnew;
    }

    float inv = 1.0f / l;
    float4* op = (float4*)(g_attn + ((size_t)b * SEQ + qi) * DMODEL + h * DKV);
#pragma unroll
    for (int i = 0; i < 16; i++) {
        float4 v = o4[i];
        v.x *= inv; v.y *= inv; v.z *= inv; v.w *= inv;
        op[i] = v;
    }
}

// ---------------- launcher ---------------------------------------------------
extern "C" void kernel_launch(void* const* d_in, const int* in_sizes, int n_in,
                              void* d_out, int out_size) {
    const float* hidden = (const float*)d_in[0];
    const float* Wq     = (const float*)d_in[1];
    const float* Wk     = (const float*)d_in[2];
    const float* Wv     = (const float*)d_in[3];
    const float* Wo     = (const float*)d_in[4];
    const float* table  = (const float*)d_in[5];
    float* out = (float*)d_out;

    bias_kernel<<<(HEADS * BIAS_PAD + 255) / 256, 256>>>(table);

    dim3 ggrid(DMODEL / 128, MTOT / 128);   // 8 x 32
    sgemm128<<<ggrid, 256>>>(hidden, 0, Wq, nullptr, 1, 1);
    sgemm128<<<ggrid, 256>>>(hidden, 0, Wk, nullptr, 2, 1);
    sgemm128<<<ggrid, 256>>>(hidden, 0, Wv, nullptr, 3, 1);

    attn_kernel<<<dim3(SEQ / QR, HEADS, BATCH), 128>>>();

    sgemm128<<<ggrid, 256>>>(nullptr, 1, Wo, out, 0, 0);
}